// round 4
// baseline (speedup 1.0000x reference)
#include <cuda_runtime.h>
#include <cuda_bf16.h>

// DynamicSparseAttention: B=4,H=16,S=2048,D=64
// out layout in d_out (f32): [out: BH*S*D][attn: BH*S*S][tau: BH*S]
#define S_LEN 2048
#define D_DIM 64
#define BH    64

// -------------------------------------------------------------------------
// Kernel 1: scores = (Q @ K^T) * scale, written (pre-softmax) into attn buf.
// 64x64 CTA tile, 16x16 threads, 4x4 per-thread microtile. FFMA-bound.
// -------------------------------------------------------------------------
__global__ __launch_bounds__(256) void dsa_scores_kernel(
    const float* __restrict__ q, const float* __restrict__ k,
    float* __restrict__ attn)
{
    __shared__ float Qs[64][65];
    __shared__ float Ks[64][65];

    const int bh = blockIdx.z;
    const int qt = blockIdx.y;
    const int kt = blockIdx.x;
    const int tx = threadIdx.x, ty = threadIdx.y;
    const int tid = ty * 16 + tx;

    const float* Qb = q + ((size_t)bh * S_LEN + (size_t)qt * 64) * D_DIM;
    const float* Kb = k + ((size_t)bh * S_LEN + (size_t)kt * 64) * D_DIM;

    #pragma unroll
    for (int t = tid; t < 64 * 64; t += 256) {
        int r = t >> 6, c = t & 63;
        Qs[r][c] = Qb[r * D_DIM + c];
        Ks[r][c] = Kb[r * D_DIM + c];
    }
    __syncthreads();

    float acc[4][4] = {};
    #pragma unroll 8
    for (int d = 0; d < 64; d++) {
        float a[4], b[4];
        #pragma unroll
        for (int i = 0; i < 4; i++) a[i] = Qs[ty * 4 + i][d];
        #pragma unroll
        for (int j = 0; j < 4; j++) b[j] = Ks[tx * 4 + j][d];
        #pragma unroll
        for (int i = 0; i < 4; i++)
            #pragma unroll
            for (int j = 0; j < 4; j++)
                acc[i][j] = fmaf(a[i], b[j], acc[i][j]);
    }

    const float scale = 0.125f;  // D^-0.5, D=64
    float* Ab = attn + ((size_t)bh * S_LEN + (size_t)qt * 64) * S_LEN + (size_t)kt * 64;
    #pragma unroll
    for (int i = 0; i < 4; i++) {
        float4 vo = make_float4(acc[i][0] * scale, acc[i][1] * scale,
                                acc[i][2] * scale, acc[i][3] * scale);
        *(float4*)(Ab + (size_t)(ty * 4 + i) * S_LEN + tx * 4) = vo;
    }
}

// -------------------------------------------------------------------------
// Kernel 2: per-row variance (ddof=1) -> tau -> softmax(scores/tau) in place.
// One CTA per row (131072 rows), row cached in SMEM. DRAM-bound (~2.15 GB).
// -------------------------------------------------------------------------
__global__ __launch_bounds__(256) void dsa_softvar_kernel(
    float* __restrict__ attn, float* __restrict__ tau_out)
{
    __shared__ float s[S_LEN];
    __shared__ float redA[8], redB[8], redC[8];
    __shared__ float bc[2];

    const size_t row = blockIdx.x;
    float* rowp = attn + row * (size_t)S_LEN;
    const int tid = threadIdx.x;
    const int lane = tid & 31, wid = tid >> 5;

    float4* s4 = (float4*)s;
    float4* r4 = (float4*)rowp;

    float sum = 0.f, sq = 0.f, mx = -3.402823466e38f;
    #pragma unroll
    for (int i = 0; i < 2; i++) {
        float4 f = r4[tid + i * 256];
        s4[tid + i * 256] = f;
        sum += f.x + f.y + f.z + f.w;
        sq = fmaf(f.x, f.x, sq); sq = fmaf(f.y, f.y, sq);
        sq = fmaf(f.z, f.z, sq); sq = fmaf(f.w, f.w, sq);
        mx = fmaxf(mx, fmaxf(fmaxf(f.x, f.y), fmaxf(f.z, f.w)));
    }
    #pragma unroll
    for (int o = 16; o; o >>= 1) {
        sum += __shfl_xor_sync(0xffffffffu, sum, o);
        sq  += __shfl_xor_sync(0xffffffffu, sq, o);
        mx   = fmaxf(mx, __shfl_xor_sync(0xffffffffu, mx, o));
    }
    if (lane == 0) { redA[wid] = sum; redB[wid] = sq; redC[wid] = mx; }
    __syncthreads();

    if (tid == 0) {
        float St = 0.f, Qt = 0.f, Mt = -3.402823466e38f;
        #pragma unroll
        for (int i = 0; i < 8; i++) {
            St += redA[i]; Qt += redB[i]; Mt = fmaxf(Mt, redC[i]);
        }
        float mean = St * (1.0f / S_LEN);
        float var  = (Qt - St * mean) * (1.0f / (S_LEN - 1));  // ddof=1
        float t = 1.0f / (1.0f + var);                          // BASE_TAU=1
        t = fmaxf(t, 0.3f);                                     // MIN_TAU
        bc[0] = 1.0f / t;
        bc[1] = Mt;
        tau_out[row] = t;
    }
    __syncthreads();

    const float itau = bc[0];
    const float m = bc[1];

    float lsum = 0.f;
    #pragma unroll
    for (int i = 0; i < 2; i++) {
        float4 f = s4[tid + i * 256];
        f.x = __expf((f.x - m) * itau);
        f.y = __expf((f.y - m) * itau);
        f.z = __expf((f.z - m) * itau);
        f.w = __expf((f.w - m) * itau);
        s4[tid + i * 256] = f;
        lsum += f.x + f.y + f.z + f.w;
    }
    #pragma unroll
    for (int o = 16; o; o >>= 1) lsum += __shfl_xor_sync(0xffffffffu, lsum, o);
    if (lane == 0) redA[wid] = lsum;
    __syncthreads();
    if (tid == 0) {
        float d = 0.f;
        #pragma unroll
        for (int i = 0; i < 8; i++) d += redA[i];
        bc[0] = 1.0f / d;
    }
    __syncthreads();

    const float rd = bc[0];
    #pragma unroll
    for (int i = 0; i < 2; i++) {
        float4 f = s4[tid + i * 256];
        f.x *= rd; f.y *= rd; f.z *= rd; f.w *= rd;
        r4[tid + i * 256] = f;
    }
}

// -------------------------------------------------------------------------
// Kernel 3: out = attn @ V. 64(q)x64(d) CTA tile, K=2048 loop in 64-chunks.
// -------------------------------------------------------------------------
__global__ __launch_bounds__(256) void dsa_av_kernel(
    const float* __restrict__ attn, const float* __restrict__ v,
    float* __restrict__ out)
{
    __shared__ float As[64][65];
    __shared__ float Vs[64][65];

    const int bh = blockIdx.y;
    const int qt = blockIdx.x;
    const int tx = threadIdx.x, ty = threadIdx.y;
    const int tid = ty * 16 + tx;

    const float* Ab = attn + ((size_t)bh * S_LEN + (size_t)qt * 64) * S_LEN;
    const float* Vb = v + (size_t)bh * S_LEN * D_DIM;

    float acc[4][4] = {};

    for (int kk = 0; kk < S_LEN; kk += 64) {
        #pragma unroll
        for (int t = tid; t < 64 * 64; t += 256) {
            int r = t >> 6, c = t & 63;
            As[r][c] = Ab[(size_t)r * S_LEN + kk + c];
            Vs[r][c] = Vb[(size_t)(kk + r) * D_DIM + c];
        }
        __syncthreads();

        #pragma unroll 8
        for (int kc = 0; kc < 64; kc++) {
            float a[4], b[4];
            #pragma unroll
            for (int i = 0; i < 4; i++) a[i] = As[ty * 4 + i][kc];
            #pragma unroll
            for (int j = 0; j < 4; j++) b[j] = Vs[kc][tx * 4 + j];
            #pragma unroll
            for (int i = 0; i < 4; i++)
                #pragma unroll
                for (int j = 0; j < 4; j++)
                    acc[i][j] = fmaf(a[i], b[j], acc[i][j]);
        }
        __syncthreads();
    }

    float* Ob = out + ((size_t)bh * S_LEN + (size_t)qt * 64) * D_DIM;
    #pragma unroll
    for (int i = 0; i < 4; i++) {
        float4 vo = make_float4(acc[i][0], acc[i][1], acc[i][2], acc[i][3]);
        *(float4*)(Ob + (size_t)(ty * 4 + i) * D_DIM + tx * 4) = vo;
    }
}

// -------------------------------------------------------------------------
extern "C" void kernel_launch(void* const* d_in, const int* in_sizes, int n_in,
                              void* d_out, int out_size)
{
    const float* q = (const float*)d_in[0];
    const float* k = (const float*)d_in[1];
    const float* v = (const float*)d_in[2];

    float* outp = (float*)d_out;                                   // BH*S*D
    float* attn = outp + (size_t)BH * S_LEN * D_DIM;               // BH*S*S
    float* tau  = attn + (size_t)BH * S_LEN * S_LEN;               // BH*S

    dim3 blk(16, 16);
    dsa_scores_kernel<<<dim3(S_LEN / 64, S_LEN / 64, BH), blk>>>(q, k, attn);
    dsa_softvar_kernel<<<BH * S_LEN, 256>>>(attn, tau);
    dsa_av_kernel<<<dim3(S_LEN / 64, BH), blk>>>(attn, v, outp);
}

// round 5
// speedup vs baseline: 1.5975x; 1.5975x over previous
#include <cuda_runtime.h>
#include <cuda_bf16.h>

// DynamicSparseAttention: B=4,H=16,S=2048,D=64
// d_out layout (f32): [out: BH*S*D][attn: BH*S*S][tau: BH*S]
#define S_LEN 2048
#define D_DIM 64
#define BH    64

// -------------------------------------------------------------------------
// Kernel 1: scores = (Q @ K^T) * scale  (pre-softmax, into attn buffer)
// 128x128 CTA tile, 16x16 threads, 8x8 microtile. D split into two 32-halves
// to keep static smem < 48KB. a: broadcast scalar LDS; b: LDS.128 from K^T.
// -------------------------------------------------------------------------
__global__ __launch_bounds__(256, 2) void dsa_scores_kernel(
    const float* __restrict__ q, const float* __restrict__ k,
    float* __restrict__ attn)
{
    __shared__ float Qs[128][36];    // [qrow][d-half]  (rowlen mult of 4 -> STS.128 ok)
    __shared__ float KsT[32][132];   // [d-half][kcol]  (528B rows, 16B aligned)

    const int bh = blockIdx.z, qt = blockIdx.y, kt = blockIdx.x;
    const int tid = threadIdx.x;
    const int tx = tid & 15, ty = tid >> 4;

    const float* Qb = q + ((size_t)bh * S_LEN + (size_t)qt * 128) * D_DIM;
    const float* Kb = k + ((size_t)bh * S_LEN + (size_t)kt * 128) * D_DIM;

    float acc[8][8] = {};

    #pragma unroll
    for (int half = 0; half < 2; ++half) {
        if (half) __syncthreads();  // previous compute done before overwrite

        // Load Q half-tile: 128 rows x 32 d = 1024 float4, 4 per thread
        #pragma unroll
        for (int i = 0; i < 4; i++) {
            int idx = tid + i * 256;
            int r = idx >> 3, c4 = idx & 7;
            float4 f = *(const float4*)(Qb + r * D_DIM + half * 32 + c4 * 4);
            *(float4*)&Qs[r][c4 * 4] = f;
        }
        // Load K half-tile transposed: KsT[d][kcol]
        #pragma unroll
        for (int i = 0; i < 4; i++) {
            int idx = tid + i * 256;
            int kc = idx >> 3, c4 = idx & 7;
            float4 f = *(const float4*)(Kb + kc * D_DIM + half * 32 + c4 * 4);
            KsT[c4 * 4 + 0][kc] = f.x;
            KsT[c4 * 4 + 1][kc] = f.y;
            KsT[c4 * 4 + 2][kc] = f.z;
            KsT[c4 * 4 + 3][kc] = f.w;
        }
        __syncthreads();

        #pragma unroll 8
        for (int d = 0; d < 32; d++) {
            float a[8];
            #pragma unroll
            for (int i = 0; i < 8; i++) a[i] = Qs[ty * 8 + i][d];
            float4 b0 = *(const float4*)&KsT[d][tx * 8];
            float4 b1 = *(const float4*)&KsT[d][tx * 8 + 4];
            float b[8] = {b0.x, b0.y, b0.z, b0.w, b1.x, b1.y, b1.z, b1.w};
            #pragma unroll
            for (int i = 0; i < 8; i++)
                #pragma unroll
                for (int j = 0; j < 8; j++)
                    acc[i][j] = fmaf(a[i], b[j], acc[i][j]);
        }
    }

    const float scale = 0.125f;  // D^-0.5
    float* Ab = attn + ((size_t)bh * S_LEN + (size_t)qt * 128) * S_LEN
                     + (size_t)kt * 128;
    #pragma unroll
    for (int i = 0; i < 8; i++) {
        float* rowp = Ab + (size_t)(ty * 8 + i) * S_LEN + tx * 8;
        float4 v0 = make_float4(acc[i][0] * scale, acc[i][1] * scale,
                                acc[i][2] * scale, acc[i][3] * scale);
        float4 v1 = make_float4(acc[i][4] * scale, acc[i][5] * scale,
                                acc[i][6] * scale, acc[i][7] * scale);
        *(float4*)rowp = v0;
        *(float4*)(rowp + 4) = v1;
    }
}

// -------------------------------------------------------------------------
// Kernel 2: per-row variance (ddof=1) -> tau -> softmax(scores/tau) in place.
// One CTA per row; row cached in SMEM; single DRAM read + single write.
// -------------------------------------------------------------------------
__global__ __launch_bounds__(256) void dsa_softvar_kernel(
    float* __restrict__ attn, float* __restrict__ tau_out)
{
    __shared__ float s[S_LEN];
    __shared__ float redA[8], redB[8], redC[8];
    __shared__ float bc[2];

    const size_t row = blockIdx.x;
    float* rowp = attn + row * (size_t)S_LEN;
    const int tid = threadIdx.x;
    const int lane = tid & 31, wid = tid >> 5;

    float4* s4 = (float4*)s;
    float4* r4 = (float4*)rowp;

    float sum = 0.f, sq = 0.f, mx = -3.402823466e38f;
    #pragma unroll
    for (int i = 0; i < 2; i++) {
        float4 f = r4[tid + i * 256];
        s4[tid + i * 256] = f;
        sum += f.x + f.y + f.z + f.w;
        sq = fmaf(f.x, f.x, sq); sq = fmaf(f.y, f.y, sq);
        sq = fmaf(f.z, f.z, sq); sq = fmaf(f.w, f.w, sq);
        mx = fmaxf(mx, fmaxf(fmaxf(f.x, f.y), fmaxf(f.z, f.w)));
    }
    #pragma unroll
    for (int o = 16; o; o >>= 1) {
        sum += __shfl_xor_sync(0xffffffffu, sum, o);
        sq  += __shfl_xor_sync(0xffffffffu, sq, o);
        mx   = fmaxf(mx, __shfl_xor_sync(0xffffffffu, mx, o));
    }
    if (lane == 0) { redA[wid] = sum; redB[wid] = sq; redC[wid] = mx; }
    __syncthreads();

    if (tid == 0) {
        float St = 0.f, Qt = 0.f, Mt = -3.402823466e38f;
        #pragma unroll
        for (int i = 0; i < 8; i++) {
            St += redA[i]; Qt += redB[i]; Mt = fmaxf(Mt, redC[i]);
        }
        float mean = St * (1.0f / S_LEN);
        float var  = (Qt - St * mean) * (1.0f / (S_LEN - 1));  // ddof=1
        float t = 1.0f / (1.0f + var);                          // BASE_TAU=1
        t = fmaxf(t, 0.3f);                                     // MIN_TAU
        bc[0] = 1.0f / t;
        bc[1] = Mt;
        tau_out[row] = t;
    }
    __syncthreads();

    const float itau = bc[0];
    const float m = bc[1];

    float lsum = 0.f;
    #pragma unroll
    for (int i = 0; i < 2; i++) {
        float4 f = s4[tid + i * 256];
        f.x = __expf((f.x - m) * itau);
        f.y = __expf((f.y - m) * itau);
        f.z = __expf((f.z - m) * itau);
        f.w = __expf((f.w - m) * itau);
        s4[tid + i * 256] = f;
        lsum += f.x + f.y + f.z + f.w;
    }
    #pragma unroll
    for (int o = 16; o; o >>= 1) lsum += __shfl_xor_sync(0xffffffffu, lsum, o);
    if (lane == 0) redA[wid] = lsum;
    __syncthreads();
    if (tid == 0) {
        float d = 0.f;
        #pragma unroll
        for (int i = 0; i < 8; i++) d += redA[i];
        bc[0] = 1.0f / d;
    }
    __syncthreads();

    const float rd = bc[0];
    #pragma unroll
    for (int i = 0; i < 2; i++) {
        float4 f = s4[tid + i * 256];
        f.x *= rd; f.y *= rd; f.z *= rd; f.w *= rd;
        r4[tid + i * 256] = f;
    }
}

// -------------------------------------------------------------------------
// Kernel 3: out = attn @ V. 128(q)x64(d) CTA tile, 8x4 microtile,
// K streamed in chunks of 32. a: broadcast scalar LDS; b: LDS.128.
// -------------------------------------------------------------------------
__global__ __launch_bounds__(256) void dsa_av_kernel(
    const float* __restrict__ attn, const float* __restrict__ v,
    float* __restrict__ out)
{
    __shared__ float As[128][36];  // [qrow][k-chunk]
    __shared__ float Vs[32][68];   // [k-chunk][d]

    const int bh = blockIdx.y;
    const int qt = blockIdx.x;
    const int tid = threadIdx.x;
    const int tx = tid & 15, ty = tid >> 4;

    const float* Ab = attn + ((size_t)bh * S_LEN + (size_t)qt * 128) * S_LEN;
    const float* Vb = v + (size_t)bh * S_LEN * D_DIM;

    float acc[8][4] = {};

    for (int kk = 0; kk < S_LEN; kk += 32) {
        // Load A chunk: 128 x 32 = 1024 float4, 4 per thread
        #pragma unroll
        for (int i = 0; i < 4; i++) {
            int idx = tid + i * 256;
            int r = idx >> 3, c4 = idx & 7;
            float4 f = *(const float4*)(Ab + (size_t)r * S_LEN + kk + c4 * 4);
            *(float4*)&As[r][c4 * 4] = f;
        }
        // Load V chunk: 32 x 64 = 512 float4, 2 per thread
        #pragma unroll
        for (int i = 0; i < 2; i++) {
            int idx = tid + i * 256;
            int r = idx >> 4, c4 = idx & 15;
            float4 f = *(const float4*)(Vb + (size_t)(kk + r) * D_DIM + c4 * 4);
            *(float4*)&Vs[r][c4 * 4] = f;
        }
        __syncthreads();

        #pragma unroll 8
        for (int kc = 0; kc < 32; kc++) {
            float a[8];
            #pragma unroll
            for (int i = 0; i < 8; i++) a[i] = As[ty * 8 + i][kc];
            float4 b = *(const float4*)&Vs[kc][tx * 4];
            #pragma unroll
            for (int i = 0; i < 8; i++) {
                acc[i][0] = fmaf(a[i], b.x, acc[i][0]);
                acc[i][1] = fmaf(a[i], b.y, acc[i][1]);
                acc[i][2] = fmaf(a[i], b.z, acc[i][2]);
                acc[i][3] = fmaf(a[i], b.w, acc[i][3]);
            }
        }
        __syncthreads();
    }

    float* Ob = out + ((size_t)bh * S_LEN + (size_t)qt * 128) * D_DIM;
    #pragma unroll
    for (int i = 0; i < 8; i++) {
        float4 vo = make_float4(acc[i][0], acc[i][1], acc[i][2], acc[i][3]);
        *(float4*)(Ob + (size_t)(ty * 8 + i) * D_DIM + tx * 4) = vo;
    }
}

// -------------------------------------------------------------------------
extern "C" void kernel_launch(void* const* d_in, const int* in_sizes, int n_in,
                              void* d_out, int out_size)
{
    const float* q = (const float*)d_in[0];
    const float* k = (const float*)d_in[1];
    const float* v = (const float*)d_in[2];

    float* outp = (float*)d_out;                                   // BH*S*D
    float* attn = outp + (size_t)BH * S_LEN * D_DIM;               // BH*S*S
    float* tau  = attn + (size_t)BH * S_LEN * S_LEN;               // BH*S

    dsa_scores_kernel<<<dim3(S_LEN / 128, S_LEN / 128, BH), 256>>>(q, k, attn);
    dsa_softvar_kernel<<<BH * S_LEN, 256>>>(attn, tau);
    dsa_av_kernel<<<dim3(S_LEN / 128, BH), 256>>>(attn, v, outp);
}

// round 7
// speedup vs baseline: 2.8144x; 1.7617x over previous
#include <cuda_runtime.h>
#include <cuda_bf16.h>
#include <cstdint>

// DynamicSparseAttention: B=4,H=16,S=2048,D=64
// d_out layout (f32): [out: BH*S*D][attn: BH*S*S][tau: BH*S]
#define S_LEN 2048
#define D_DIM 64
#define BH    64

// ---------------------------------------------------------------- helpers
__device__ __forceinline__ uint32_t smem_u32(const void* p) {
    uint32_t a;
    asm("{ .reg .u64 t; cvta.to.shared.u64 t, %1; cvt.u32.u64 %0, t; }"
        : "=r"(a) : "l"(p));
    return a;
}

// 128B-row tile, 16B-chunk XOR swizzle: offset of (row, chunk16B)
__device__ __forceinline__ uint32_t toff(int r, int ch) {
    return (uint32_t)(r * 128 + ((ch ^ (r & 7)) << 4));
}

__device__ __forceinline__ void ldmx4(uint32_t* r, uint32_t a) {
    asm volatile("ldmatrix.sync.aligned.m8n8.x4.shared.b16 {%0,%1,%2,%3}, [%4];"
        : "=r"(r[0]), "=r"(r[1]), "=r"(r[2]), "=r"(r[3]) : "r"(a));
}
__device__ __forceinline__ void ldmx2(uint32_t* r, uint32_t a) {
    asm volatile("ldmatrix.sync.aligned.m8n8.x2.shared.b16 {%0,%1}, [%2];"
        : "=r"(r[0]), "=r"(r[1]) : "r"(a));
}
__device__ __forceinline__ void ldmx2t(uint32_t* r, uint32_t a) {
    asm volatile("ldmatrix.sync.aligned.m8n8.x2.trans.shared.b16 {%0,%1}, [%2];"
        : "=r"(r[0]), "=r"(r[1]) : "r"(a));
}
__device__ __forceinline__ void mma_bf16(float* c, const uint32_t* a, const uint32_t* b) {
    asm volatile(
        "mma.sync.aligned.m16n8k16.row.col.f32.bf16.bf16.f32 "
        "{%0,%1,%2,%3}, {%4,%5,%6,%7}, {%8,%9}, {%0,%1,%2,%3};"
        : "+f"(c[0]), "+f"(c[1]), "+f"(c[2]), "+f"(c[3])
        : "r"(a[0]), "r"(a[1]), "r"(a[2]), "r"(a[3]), "r"(b[0]), "r"(b[1]));
}

__device__ __forceinline__ uint32_t bfpair(float a, float b) {
    __nv_bfloat162 t;
    t.x = __float2bfloat16(a);
    t.y = __float2bfloat16(b);
    return *reinterpret_cast<uint32_t*>(&t);
}
// split 8 floats into 8 bf16 hi (uint4) + 8 bf16 lo (uint4)
__device__ __forceinline__ void pack8(const float* f, uint4& hi, uint4& lo) {
    float r[8];
    #pragma unroll
    for (int j = 0; j < 8; j++)
        r[j] = f[j] - __bfloat162float(__float2bfloat16(f[j]));
    hi = make_uint4(bfpair(f[0], f[1]), bfpair(f[2], f[3]),
                    bfpair(f[4], f[5]), bfpair(f[6], f[7]));
    lo = make_uint4(bfpair(r[0], r[1]), bfpair(r[2], r[3]),
                    bfpair(r[4], r[5]), bfpair(r[6], r[7]));
}

// -------------------------------------------------------------------------
// Kernel 1: scores = (Q*scale) K^T via mma.sync bf16 hi/lo 3-term split.
// CTA: 128q x 64k, K=64. 8 warps (4m x 2n), warp tile 32x32.
// SMEM: QHI 16K | QLO 16K | KHI 8K | KLO 8K  = 48KB static.
// -------------------------------------------------------------------------
__global__ __launch_bounds__(256, 2) void dsa_scores_kernel(
    const float* __restrict__ q, const float* __restrict__ k,
    float* __restrict__ attn)
{
    __shared__ __align__(16) char sm[49152];
    const uint32_t QHI = 0, QLO = 16384, KHI = 32768, KLO = 40960;
    const uint32_t sb = smem_u32(sm);

    const int tid = threadIdx.x, lane = tid & 31, wid = tid >> 5;
    const int bh = blockIdx.z, qt = blockIdx.y, kt = blockIdx.x;

    const float* Qb = q + ((size_t)bh * S_LEN + (size_t)qt * 128) * D_DIM;
    const float* Kb = k + ((size_t)bh * S_LEN + (size_t)kt * 64) * D_DIM;

    // Q: 128 rows x 8 chunks of 8 floats, scaled by 0.125 (exact)
    #pragma unroll
    for (int i = 0; i < 4; i++) {
        int idx = tid + i * 256;
        int r = idx >> 3, ch = idx & 7;
        float4 f0 = *(const float4*)(Qb + r * D_DIM + ch * 8);
        float4 f1 = *(const float4*)(Qb + r * D_DIM + ch * 8 + 4);
        float f[8] = {f0.x*0.125f, f0.y*0.125f, f0.z*0.125f, f0.w*0.125f,
                      f1.x*0.125f, f1.y*0.125f, f1.z*0.125f, f1.w*0.125f};
        uint4 hi, lo; pack8(f, hi, lo);
        uint32_t o = toff(r, ch);
        *(uint4*)(sm + QHI + o) = hi;
        *(uint4*)(sm + QLO + o) = lo;
    }
    // K: 64 rows x 8 chunks
    #pragma unroll
    for (int i = 0; i < 2; i++) {
        int idx = tid + i * 256;
        int r = idx >> 3, ch = idx & 7;
        float4 f0 = *(const float4*)(Kb + r * D_DIM + ch * 8);
        float4 f1 = *(const float4*)(Kb + r * D_DIM + ch * 8 + 4);
        float f[8] = {f0.x, f0.y, f0.z, f0.w, f1.x, f1.y, f1.z, f1.w};
        uint4 hi, lo; pack8(f, hi, lo);
        uint32_t o = toff(r, ch);
        *(uint4*)(sm + KHI + o) = hi;
        *(uint4*)(sm + KLO + o) = lo;
    }
    __syncthreads();

    const int wm = wid >> 1, wn = wid & 1;
    // A ldmatrix lane mapping (x4): mat = lane>>3
    const int alr = lane & 7, alm = (lane >> 3) & 1, alk = lane >> 4;
    // B ldmatrix lane mapping (x2): lanes 0..15
    const int l16 = lane & 15, blr = l16 & 7, blk = l16 >> 3;

    float acc[2][4][4] = {};

    #pragma unroll
    for (int ks = 0; ks < 4; ks++) {
        uint32_t ah[2][4], al[2][4];
        #pragma unroll
        for (int mi = 0; mi < 2; mi++) {
            int row = wm * 32 + mi * 16 + alr + alm * 8;
            uint32_t o = toff(row, ks * 2 + alk);
            ldmx4(ah[mi], sb + QHI + o);
            ldmx4(al[mi], sb + QLO + o);
        }
        uint32_t bh_[4][2], bl_[4][2];
        #pragma unroll
        for (int ni = 0; ni < 4; ni++) {
            int nrow = wn * 32 + ni * 8 + blr;
            uint32_t o = toff(nrow, ks * 2 + blk);
            ldmx2(bh_[ni], sb + KHI + o);
            ldmx2(bl_[ni], sb + KLO + o);
        }
        #pragma unroll
        for (int mi = 0; mi < 2; mi++)
            #pragma unroll
            for (int ni = 0; ni < 4; ni++) {
                mma_bf16(acc[mi][ni], ah[mi], bh_[ni]);
                mma_bf16(acc[mi][ni], ah[mi], bl_[ni]);
                mma_bf16(acc[mi][ni], al[mi], bh_[ni]);
            }
    }

    // store: C frag (row=lane/4, col=(lane%4)*2), rows +8 for c2/c3
    const int qr = lane >> 2, qc = (lane & 3) * 2;
    float* base = attn + ((size_t)bh * S_LEN + (size_t)qt * 128) * S_LEN
                       + (size_t)kt * 64;
    #pragma unroll
    for (int mi = 0; mi < 2; mi++) {
        #pragma unroll
        for (int ni = 0; ni < 4; ni++) {
            int row = wm * 32 + mi * 16 + qr;
            int col = wn * 32 + ni * 8 + qc;
            float2 v0 = make_float2(acc[mi][ni][0], acc[mi][ni][1]);
            float2 v1 = make_float2(acc[mi][ni][2], acc[mi][ni][3]);
            *(float2*)(base + (size_t)row * S_LEN + col) = v0;
            *(float2*)(base + (size_t)(row + 8) * S_LEN + col) = v1;
        }
    }
}

// -------------------------------------------------------------------------
// Kernel 2: per-row variance (ddof=1) -> tau -> softmax(scores/tau) in place.
// -------------------------------------------------------------------------
__global__ __launch_bounds__(256) void dsa_softvar_kernel(
    float* __restrict__ attn, float* __restrict__ tau_out)
{
    __shared__ float s[S_LEN];
    __shared__ float redA[8], redB[8], redC[8];
    __shared__ float bc[2];

    const size_t row = blockIdx.x;
    float* rowp = attn + row * (size_t)S_LEN;
    const int tid = threadIdx.x;
    const int lane = tid & 31, wid = tid >> 5;

    float4* s4 = (float4*)s;
    float4* r4 = (float4*)rowp;

    float sum = 0.f, sq = 0.f, mx = -3.402823466e38f;
    #pragma unroll
    for (int i = 0; i < 2; i++) {
        float4 f = r4[tid + i * 256];
        s4[tid + i * 256] = f;
        sum += f.x + f.y + f.z + f.w;
        sq = fmaf(f.x, f.x, sq); sq = fmaf(f.y, f.y, sq);
        sq = fmaf(f.z, f.z, sq); sq = fmaf(f.w, f.w, sq);
        mx = fmaxf(mx, fmaxf(fmaxf(f.x, f.y), fmaxf(f.z, f.w)));
    }
    #pragma unroll
    for (int o = 16; o; o >>= 1) {
        sum += __shfl_xor_sync(0xffffffffu, sum, o);
        sq  += __shfl_xor_sync(0xffffffffu, sq, o);
        mx   = fmaxf(mx, __shfl_xor_sync(0xffffffffu, mx, o));
    }
    if (lane == 0) { redA[wid] = sum; redB[wid] = sq; redC[wid] = mx; }
    __syncthreads();

    if (tid == 0) {
        float St = 0.f, Qt = 0.f, Mt = -3.402823466e38f;
        #pragma unroll
        for (int i = 0; i < 8; i++) {
            St += redA[i]; Qt += redB[i]; Mt = fmaxf(Mt, redC[i]);
        }
        float mean = St * (1.0f / S_LEN);
        float var  = (Qt - St * mean) * (1.0f / (S_LEN - 1));  // ddof=1
        float t = 1.0f / (1.0f + var);                          // BASE_TAU=1
        t = fmaxf(t, 0.3f);                                     // MIN_TAU
        bc[0] = 1.0f / t;
        bc[1] = Mt;
        tau_out[row] = t;
    }
    __syncthreads();

    const float itau = bc[0];
    const float m = bc[1];

    float lsum = 0.f;
    #pragma unroll
    for (int i = 0; i < 2; i++) {
        float4 f = s4[tid + i * 256];
        f.x = __expf((f.x - m) * itau);
        f.y = __expf((f.y - m) * itau);
        f.z = __expf((f.z - m) * itau);
        f.w = __expf((f.w - m) * itau);
        s4[tid + i * 256] = f;
        lsum += f.x + f.y + f.z + f.w;
    }
    #pragma unroll
    for (int o = 16; o; o >>= 1) lsum += __shfl_xor_sync(0xffffffffu, lsum, o);
    if (lane == 0) redA[wid] = lsum;
    __syncthreads();
    if (tid == 0) {
        float d = 0.f;
        #pragma unroll
        for (int i = 0; i < 8; i++) d += redA[i];
        bc[0] = 1.0f / d;
    }
    __syncthreads();

    const float rd = bc[0];
    #pragma unroll
    for (int i = 0; i < 2; i++) {
        float4 f = s4[tid + i * 256];
        f.x *= rd; f.y *= rd; f.z *= rd; f.w *= rd;
        r4[tid + i * 256] = f;
    }
}

// -------------------------------------------------------------------------
// Kernel 3: out = attn @ V via mma.sync bf16 hi/lo 3-term split.
// CTA: 128q x 64d, K=2048 in 32 chunks of 64. V frags via ldmatrix.x2.trans
// straight from row-major [k][d] SMEM (no transpose pass).
// SMEM: AHI 16K | ALO 16K | VHI 8K | VLO 8K = 48KB static.
// -------------------------------------------------------------------------
__global__ __launch_bounds__(256, 2) void dsa_av_kernel(
    const float* __restrict__ attn, const float* __restrict__ v,
    float* __restrict__ out)
{
    __shared__ __align__(16) char sm[49152];
    const uint32_t AHI = 0, ALO = 16384, VHI = 32768, VLO = 40960;
    const uint32_t sb = smem_u32(sm);

    const int tid = threadIdx.x, lane = tid & 31, wid = tid >> 5;
    const int bh = blockIdx.y, qt = blockIdx.x;

    const float* Ab = attn + ((size_t)bh * S_LEN + (size_t)qt * 128) * S_LEN;
    const float* Vb = v + (size_t)bh * S_LEN * D_DIM;

    const int wm = wid >> 1, wn = wid & 1;
    const int alr = lane & 7, alm = (lane >> 3) & 1, alk = lane >> 4;
    const int l16 = lane & 15;

    float acc[2][4][4] = {};

    for (int chnk = 0; chnk < 32; chnk++) {
        const int kk = chnk * 64;

        // attn chunk: 128 rows x 8 chunks of 8 f32
        #pragma unroll
        for (int i = 0; i < 4; i++) {
            int idx = tid + i * 256;
            int r = idx >> 3, ch = idx & 7;
            float4 f0 = *(const float4*)(Ab + (size_t)r * S_LEN + kk + ch * 8);
            float4 f1 = *(const float4*)(Ab + (size_t)r * S_LEN + kk + ch * 8 + 4);
            float f[8] = {f0.x, f0.y, f0.z, f0.w, f1.x, f1.y, f1.z, f1.w};
            uint4 hi, lo; pack8(f, hi, lo);
            uint32_t o = toff(r, ch);
            *(uint4*)(sm + AHI + o) = hi;
            *(uint4*)(sm + ALO + o) = lo;
        }
        // V chunk: 64 rows (k) x 8 chunks (d)
        #pragma unroll
        for (int i = 0; i < 2; i++) {
            int idx = tid + i * 256;
            int r = idx >> 3, ch = idx & 7;
            float4 f0 = *(const float4*)(Vb + (size_t)(kk + r) * D_DIM + ch * 8);
            float4 f1 = *(const float4*)(Vb + (size_t)(kk + r) * D_DIM + ch * 8 + 4);
            float f[8] = {f0.x, f0.y, f0.z, f0.w, f1.x, f1.y, f1.z, f1.w};
            uint4 hi, lo; pack8(f, hi, lo);
            uint32_t o = toff(r, ch);
            *(uint4*)(sm + VHI + o) = hi;
            *(uint4*)(sm + VLO + o) = lo;
        }
        __syncthreads();

        #pragma unroll
        for (int ks = 0; ks < 4; ks++) {
            uint32_t ah[2][4], al[2][4];
            #pragma unroll
            for (int mi = 0; mi < 2; mi++) {
                int row = wm * 32 + mi * 16 + alr + alm * 8;
                uint32_t o = toff(row, ks * 2 + alk);
                ldmx4(ah[mi], sb + AHI + o);
                ldmx4(al[mi], sb + ALO + o);
            }
            uint32_t bh_[4][2], bl_[4][2];
            #pragma unroll
            for (int ni = 0; ni < 4; ni++) {
                // B row-major [k][d]: mat rows = k = ks*16 + l16, chunk = d/8
                int krow = ks * 16 + l16;
                int nch = (wn * 32 + ni * 8) >> 3;
                uint32_t o = toff(krow, nch);
                ldmx2t(bh_[ni], sb + VHI + o);
                ldmx2t(bl_[ni], sb + VLO + o);
            }
            #pragma unroll
            for (int mi = 0; mi < 2; mi++)
                #pragma unroll
                for (int ni = 0; ni < 4; ni++) {
                    mma_bf16(acc[mi][ni], ah[mi], bh_[ni]);
                    mma_bf16(acc[mi][ni], ah[mi], bl_[ni]);
                    mma_bf16(acc[mi][ni], al[mi], bh_[ni]);
                }
        }
        __syncthreads();
    }

    const int qr = lane >> 2, qc = (lane & 3) * 2;
    float* Ob = out + ((size_t)bh * S_LEN + (size_t)qt * 128) * D_DIM;
    #pragma unroll
    for (int mi = 0; mi < 2; mi++) {
        #pragma unroll
        for (int ni = 0; ni < 4; ni++) {
            int row = wm * 32 + mi * 16 + qr;
            int col = wn * 32 + ni * 8 + qc;
            float2 v0 = make_float2(acc[mi][ni][0], acc[mi][ni][1]);
            float2 v1 = make_float2(acc[mi][ni][2], acc[mi][ni][3]);
            *(float2*)(Ob + (size_t)row * D_DIM + col) = v0;
            *(float2*)(Ob + (size_t)(row + 8) * D_DIM + col) = v1;
        }
    }
}

// -------------------------------------------------------------------------
extern "C" void kernel_launch(void* const* d_in, const int* in_sizes, int n_in,
                              void* d_out, int out_size)
{
    const float* q = (const float*)d_in[0];
    const float* k = (const float*)d_in[1];
    const float* v = (const float*)d_in[2];

    float* outp = (float*)d_out;                                   // BH*S*D
    float* attn = outp + (size_t)BH * S_LEN * D_DIM;               // BH*S*S
    float* tau  = attn + (size_t)BH * S_LEN * S_LEN;               // BH*S

    dsa_scores_kernel<<<dim3(S_LEN / 64, S_LEN / 128, BH), 256>>>(q, k, attn);
    dsa_softvar_kernel<<<BH * S_LEN, 256>>>(attn, tau);
    dsa_av_kernel<<<dim3(S_LEN / 128, BH), 256>>>(attn, v, outp);
}